// round 1
// baseline (speedup 1.0000x reference)
#include <cuda_runtime.h>
#include <cstddef>

#define BB 2
#define TQ 2048
#define TK 2048
#define DIN 1024
#define DOUT 1024
#define NH 16
#define HD 64

// Scratch (no cudaMalloc allowed): projected Q/K/V and attention output X.
__device__ float g_q[(size_t)BB * TQ * DOUT];
__device__ float g_k[(size_t)BB * TK * DOUT];
__device__ float g_v[(size_t)BB * TK * DOUT];
__device__ float g_x[(size_t)BB * TQ * DOUT];

// ---------------------------------------------------------------------------
// GEMM with fused bias: Y[M,N] = X[M,K] @ W[N,K]^T + bias[N]
// 64x64 block tile, 16 k-slice, 256 threads, 4x4 register tile, float4 LDS.
// ---------------------------------------------------------------------------
__global__ __launch_bounds__(256) void gemm_bias_kernel(
    const float* __restrict__ X, const float* __restrict__ W,
    const float* __restrict__ bias, float* __restrict__ Y,
    int M, int N, int K) {
    __shared__ float As[16][64];  // [k][m]
    __shared__ float Bs[16][64];  // [k][n]

    const int tid = threadIdx.x;
    const int tx = tid & 15;
    const int ty = tid >> 4;
    const int row0 = blockIdx.y * 64;
    const int col0 = blockIdx.x * 64;

    float acc[4][4] = {};

    for (int k0 = 0; k0 < K; k0 += 16) {
        // Load 64x16 A-slice and 64x16 W-slice (4 elems/thread each),
        // storing transposed so the inner loop reads float4-contiguous.
#pragma unroll
        for (int i = 0; i < 4; i++) {
            int idx = tid + i * 256;
            int m = idx >> 4;
            int kk = idx & 15;
            As[kk][m] = X[(size_t)(row0 + m) * K + k0 + kk];
            Bs[kk][m] = W[(size_t)(col0 + m) * K + k0 + kk];
        }
        __syncthreads();

#pragma unroll
        for (int kk = 0; kk < 16; kk++) {
            float4 a = *(const float4*)&As[kk][ty * 4];
            float4 b = *(const float4*)&Bs[kk][tx * 4];
            acc[0][0] += a.x * b.x; acc[0][1] += a.x * b.y; acc[0][2] += a.x * b.z; acc[0][3] += a.x * b.w;
            acc[1][0] += a.y * b.x; acc[1][1] += a.y * b.y; acc[1][2] += a.y * b.z; acc[1][3] += a.y * b.w;
            acc[2][0] += a.z * b.x; acc[2][1] += a.z * b.y; acc[2][2] += a.z * b.z; acc[2][3] += a.z * b.w;
            acc[3][0] += a.w * b.x; acc[3][1] += a.w * b.y; acc[3][2] += a.w * b.z; acc[3][3] += a.w * b.w;
        }
        __syncthreads();
    }

#pragma unroll
    for (int i = 0; i < 4; i++) {
        int r = row0 + ty * 4 + i;
#pragma unroll
        for (int j = 0; j < 4; j++) {
            int c = col0 + tx * 4 + j;
            Y[(size_t)r * N + c] = acc[i][j] + bias[c];
        }
    }
}

// ---------------------------------------------------------------------------
// Flash-attention (fp32, non-causal). One block handles 64 queries of one
// (batch, head). Streams 64-key tiles with online softmax. Q/K stored
// transposed in smem (pad 4 to tame bank conflicts), P staged transposed.
// ---------------------------------------------------------------------------
#define QPAD 68
#define SM_QT 0                     // QsT[64(d)][68] (q index inner)
#define SM_KT (64 * QPAD)           // KsT[64(d)][68]
#define SM_V  (2 * 64 * QPAD)       // Vs[64(k)][64(d)]
#define SM_PT (2 * 64 * QPAD + 64 * 64)  // PsT[64(k)][68] (q index inner)
#define SMEM_ATTN_BYTES ((3 * 64 * QPAD + 64 * 64) * 4)

__global__ __launch_bounds__(256) void attn_kernel(
    const float* __restrict__ gq, const float* __restrict__ gk,
    const float* __restrict__ gv, float* __restrict__ gx) {
    extern __shared__ float sm[];
    float* QsT = sm + SM_QT;
    float* KsT = sm + SM_KT;
    float* Vs  = sm + SM_V;
    float* PsT = sm + SM_PT;

    const int tid = threadIdx.x;
    const int tx = tid & 15;
    const int ty = tid >> 4;
    const int q0 = blockIdx.x * 64;
    const int h  = blockIdx.y;
    const int b  = blockIdx.z;

    const float* Qg = gq + ((size_t)b * TQ + q0) * DOUT + h * HD;
    const float* Kg = gk + (size_t)b * TK * DOUT + h * HD;
    const float* Vg = gv + (size_t)b * TK * DOUT + h * HD;

    // Load Q tile (transposed), folding in the 1/sqrt(HD) = 0.125 scale.
#pragma unroll
    for (int i = 0; i < 16; i++) {
        int idx = tid + i * 256;
        int qq = idx >> 6;
        int d  = idx & 63;
        QsT[d * QPAD + qq] = Qg[(size_t)qq * DOUT + d] * 0.125f;
    }

    float o[4][4] = {};
    float mrow[4], lrow[4];
#pragma unroll
    for (int i = 0; i < 4; i++) { mrow[i] = -1e30f; lrow[i] = 0.0f; }

    for (int kt = 0; kt < TK; kt += 64) {
        __syncthreads();  // previous PV pass done before K/V/P reuse
#pragma unroll
        for (int i = 0; i < 16; i++) {
            int idx = tid + i * 256;
            int kk = idx >> 6;
            int d  = idx & 63;
            float kv = Kg[(size_t)(kt + kk) * DOUT + d];
            float vv = Vg[(size_t)(kt + kk) * DOUT + d];
            KsT[d * QPAD + kk] = kv;
            Vs[kk * 64 + d]    = vv;
        }
        __syncthreads();

        // S = Qs @ Ks^T  (rows q = ty*4.., cols k = tx*4..)
        float s[4][4] = {};
#pragma unroll 8
        for (int d = 0; d < 64; d++) {
            float4 a = *(const float4*)&QsT[d * QPAD + ty * 4];
            float4 bk = *(const float4*)&KsT[d * QPAD + tx * 4];
            s[0][0] += a.x * bk.x; s[0][1] += a.x * bk.y; s[0][2] += a.x * bk.z; s[0][3] += a.x * bk.w;
            s[1][0] += a.y * bk.x; s[1][1] += a.y * bk.y; s[1][2] += a.y * bk.z; s[1][3] += a.y * bk.w;
            s[2][0] += a.z * bk.x; s[2][1] += a.z * bk.y; s[2][2] += a.z * bk.z; s[2][3] += a.z * bk.w;
            s[3][0] += a.w * bk.x; s[3][1] += a.w * bk.y; s[3][2] += a.w * bk.z; s[3][3] += a.w * bk.w;
        }

        // Online softmax per row; row stats reduced over the 16-lane tx group.
#pragma unroll
        for (int i = 0; i < 4; i++) {
            float rm = fmaxf(fmaxf(s[i][0], s[i][1]), fmaxf(s[i][2], s[i][3]));
#pragma unroll
            for (int w = 1; w < 16; w <<= 1)
                rm = fmaxf(rm, __shfl_xor_sync(0xffffffffu, rm, w, 16));
            float mnew = fmaxf(mrow[i], rm);
            float c = __expf(mrow[i] - mnew);
            mrow[i] = mnew;
            float rs = 0.0f;
#pragma unroll
            for (int j = 0; j < 4; j++) {
                float p = __expf(s[i][j] - mnew);
                s[i][j] = p;
                rs += p;
            }
#pragma unroll
            for (int w = 1; w < 16; w <<= 1)
                rs += __shfl_xor_sync(0xffffffffu, rs, w, 16);
            lrow[i] = lrow[i] * c + rs;
#pragma unroll
            for (int j = 0; j < 4; j++) {
                o[i][j] *= c;
                PsT[(tx * 4 + j) * QPAD + (ty * 4 + i)] = s[i][j];
            }
        }
        __syncthreads();

        // O += P @ V   (rows q = ty*4.., cols d = tx*4..)
#pragma unroll 8
        for (int kk = 0; kk < 64; kk++) {
            float4 a = *(const float4*)&PsT[kk * QPAD + ty * 4];
            float4 bv = *(const float4*)&Vs[kk * 64 + tx * 4];
            o[0][0] += a.x * bv.x; o[0][1] += a.x * bv.y; o[0][2] += a.x * bv.z; o[0][3] += a.x * bv.w;
            o[1][0] += a.y * bv.x; o[1][1] += a.y * bv.y; o[1][2] += a.y * bv.z; o[1][3] += a.y * bv.w;
            o[2][0] += a.z * bv.x; o[2][1] += a.z * bv.y; o[2][2] += a.z * bv.z; o[2][3] += a.z * bv.w;
            o[3][0] += a.w * bv.x; o[3][1] += a.w * bv.y; o[3][2] += a.w * bv.z; o[3][3] += a.w * bv.w;
        }
    }

    // Normalize and write x in [B, T, H*HD] layout.
#pragma unroll
    for (int i = 0; i < 4; i++) {
        float inv_l = 1.0f / lrow[i];
        size_t row = (size_t)b * TQ + q0 + ty * 4 + i;
#pragma unroll
        for (int j = 0; j < 4; j++) {
            gx[row * DOUT + h * HD + tx * 4 + j] = o[i][j] * inv_l;
        }
    }
}

// ---------------------------------------------------------------------------
// Launch
// ---------------------------------------------------------------------------
extern "C" void kernel_launch(void* const* d_in, const int* in_sizes, int n_in,
                              void* d_out, int out_size) {
    const float* q  = (const float*)d_in[0];
    const float* k  = (const float*)d_in[1];
    const float* v  = (const float*)d_in[2];
    const float* Wq = (const float*)d_in[3];
    const float* bq = (const float*)d_in[4];
    const float* Wk = (const float*)d_in[5];
    const float* bk = (const float*)d_in[6];
    const float* Wv = (const float*)d_in[7];
    const float* bv = (const float*)d_in[8];
    const float* Wo = (const float*)d_in[9];
    const float* bo = (const float*)d_in[10];
    float* out = (float*)d_out;

    float *pq, *pk, *pv, *px;
    cudaGetSymbolAddress((void**)&pq, g_q);
    cudaGetSymbolAddress((void**)&pk, g_k);
    cudaGetSymbolAddress((void**)&pv, g_v);
    cudaGetSymbolAddress((void**)&px, g_x);

    dim3 blk(256);
    dim3 gproj(DOUT / 64, (BB * TQ) / 64);

    gemm_bias_kernel<<<gproj, blk>>>(q, Wq, bq, pq, BB * TQ, DOUT, DIN);
    gemm_bias_kernel<<<gproj, blk>>>(k, Wk, bk, pk, BB * TK, DOUT, DIN);
    gemm_bias_kernel<<<gproj, blk>>>(v, Wv, bv, pv, BB * TK, DOUT, DIN);

    cudaFuncSetAttribute(attn_kernel,
                         cudaFuncAttributeMaxDynamicSharedMemorySize,
                         SMEM_ATTN_BYTES);
    attn_kernel<<<dim3(TQ / 64, NH, BB), blk, SMEM_ATTN_BYTES>>>(pq, pk, pv, px);

    gemm_bias_kernel<<<gproj, blk>>>(px, Wo, bo, out, BB * TQ, DOUT, DOUT);
}

// round 2
// speedup vs baseline: 4.1320x; 4.1320x over previous
#include <cuda_runtime.h>
#include <cstddef>

#define BB 2
#define TQ 2048
#define TK 2048
#define DIN 1024
#define DOUT 1024
#define NH 16
#define HD 64

// Scratch (no cudaMalloc allowed): projected Q/K/V and attention output X.
__device__ float g_q[(size_t)BB * TQ * DOUT];
__device__ float g_k[(size_t)BB * TK * DOUT];
__device__ float g_v[(size_t)BB * TK * DOUT];
__device__ float g_x[(size_t)BB * TQ * DOUT];

// ---------------------------------------------------------------------------
// TF32 helpers
// ---------------------------------------------------------------------------
__device__ __forceinline__ unsigned f2tf(float f) {
    unsigned r;
    asm("cvt.rna.tf32.f32 %0, %1;" : "=r"(r) : "f"(f));
    return r;
}

__device__ __forceinline__ void mma_tf32(float c[4],
                                         unsigned a0, unsigned a1, unsigned a2, unsigned a3,
                                         unsigned b0, unsigned b1) {
    asm volatile(
        "mma.sync.aligned.m16n8k8.row.col.f32.tf32.tf32.f32 "
        "{%0,%1,%2,%3}, {%4,%5,%6,%7}, {%8,%9}, {%0,%1,%2,%3};"
        : "+f"(c[0]), "+f"(c[1]), "+f"(c[2]), "+f"(c[3])
        : "r"(a0), "r"(a1), "r"(a2), "r"(a3), "r"(b0), "r"(b1));
}

// ---------------------------------------------------------------------------
// GEMM + bias on tensor cores: Y[M,N] = X[M,K] @ W[N,K]^T + bias[N]
// Block tile 128x128, k-slice 32, 256 threads (8 warps as 4m x 2n,
// warp tile 32x64). Fragments gathered from smem with stride 36 (== 4 mod 32
// -> conflict-free: banks 4*(lane/4) + lane%4 cover 0..31).
// ---------------------------------------------------------------------------
#define GST 36  // smem row stride (floats)

__global__ __launch_bounds__(256) void gemm_tf32_kernel(
    const float* __restrict__ X, const float* __restrict__ W,
    const float* __restrict__ bias, float* __restrict__ Y,
    int M, int N, int K) {
    __shared__ unsigned As[128 * GST];
    __shared__ unsigned Bs[128 * GST];

    const int tid = threadIdx.x;
    const int lane = tid & 31;
    const int wid = tid >> 5;
    const int wm = wid >> 1;   // 0..3
    const int wn = wid & 1;    // 0..1
    const int g = lane >> 2;   // groupID 0..7
    const int c = lane & 3;    // 0..3

    const int row0 = blockIdx.y * 128;
    const int col0 = blockIdx.x * 128;

    float acc[2][8][4];
#pragma unroll
    for (int mt = 0; mt < 2; mt++)
#pragma unroll
        for (int nt = 0; nt < 8; nt++)
#pragma unroll
            for (int j = 0; j < 4; j++) acc[mt][nt][j] = 0.0f;

    const int lrow = tid >> 3;          // 0..31 (x8 over i -> 0..127)
    const int lcol = (tid & 7) * 4;     // 0..28

    for (int k0 = 0; k0 < K; k0 += 32) {
#pragma unroll
        for (int i = 0; i < 4; i++) {
            int r = lrow + i * 32;
            float4 xa = *(const float4*)&X[(size_t)(row0 + r) * K + k0 + lcol];
            float4 wa = *(const float4*)&W[(size_t)(col0 + r) * K + k0 + lcol];
            As[r * GST + lcol + 0] = f2tf(xa.x);
            As[r * GST + lcol + 1] = f2tf(xa.y);
            As[r * GST + lcol + 2] = f2tf(xa.z);
            As[r * GST + lcol + 3] = f2tf(xa.w);
            Bs[r * GST + lcol + 0] = f2tf(wa.x);
            Bs[r * GST + lcol + 1] = f2tf(wa.y);
            Bs[r * GST + lcol + 2] = f2tf(wa.z);
            Bs[r * GST + lcol + 3] = f2tf(wa.w);
        }
        __syncthreads();

#pragma unroll
        for (int ks = 0; ks < 4; ks++) {
            const int kk = ks * 8;
            unsigned af[2][4];
#pragma unroll
            for (int mt = 0; mt < 2; mt++) {
                int ar = wm * 32 + mt * 16;
                af[mt][0] = As[(ar + g) * GST + kk + c];
                af[mt][1] = As[(ar + g + 8) * GST + kk + c];
                af[mt][2] = As[(ar + g) * GST + kk + c + 4];
                af[mt][3] = As[(ar + g + 8) * GST + kk + c + 4];
            }
            unsigned bf[8][2];
#pragma unroll
            for (int nt = 0; nt < 8; nt++) {
                int bc = wn * 64 + nt * 8 + g;
                bf[nt][0] = Bs[bc * GST + kk + c];
                bf[nt][1] = Bs[bc * GST + kk + c + 4];
            }
#pragma unroll
            for (int mt = 0; mt < 2; mt++)
#pragma unroll
                for (int nt = 0; nt < 8; nt++)
                    mma_tf32(acc[mt][nt], af[mt][0], af[mt][1], af[mt][2], af[mt][3],
                             bf[nt][0], bf[nt][1]);
        }
        __syncthreads();
    }

#pragma unroll
    for (int mt = 0; mt < 2; mt++) {
        int r0 = row0 + wm * 32 + mt * 16 + g;
#pragma unroll
        for (int nt = 0; nt < 8; nt++) {
            int cc = col0 + wn * 64 + nt * 8 + c * 2;
            float b0 = bias[cc], b1 = bias[cc + 1];
            float2 lo = {acc[mt][nt][0] + b0, acc[mt][nt][1] + b1};
            float2 hi = {acc[mt][nt][2] + b0, acc[mt][nt][3] + b1};
            *(float2*)&Y[(size_t)r0 * N + cc] = lo;
            *(float2*)&Y[(size_t)(r0 + 8) * N + cc] = hi;
        }
    }
}

// ---------------------------------------------------------------------------
// Flash-attention on tensor cores (tf32 mma, fp32 accumulate + softmax).
// Block = 128 queries of one (batch, head); 8 warps, warp owns 16 q rows.
// Q held in registers as A-fragments. K/V streamed in 64-key tiles.
// P re-fragmented through per-warp smem rows (only __syncwarp needed).
// Smem strides: Ks 68, Ps 68 (banks 4g+c), Vs 72 (banks 8c+g): conflict-free.
// ---------------------------------------------------------------------------
#define KS_ST 68
#define VS_ST 72
#define PS_ST 68
#define SM_KS 0
#define SM_VS (64 * KS_ST)
#define SM_PS (64 * KS_ST + 64 * VS_ST)
#define ATTN_SMEM_WORDS (64 * KS_ST + 64 * VS_ST + 128 * PS_ST)
#define ATTN_SMEM_BYTES (ATTN_SMEM_WORDS * 4)

__global__ __launch_bounds__(256) void attn_tf32_kernel(
    const float* __restrict__ gq, const float* __restrict__ gk,
    const float* __restrict__ gv, float* __restrict__ gx) {
    extern __shared__ unsigned sm[];
    unsigned* Ks = sm + SM_KS;
    unsigned* Vs = sm + SM_VS;
    unsigned* Ps = sm + SM_PS;

    const int tid = threadIdx.x;
    const int lane = tid & 31;
    const int w = tid >> 5;    // warp 0..7 -> q rows [w*16, w*16+16)
    const int g = lane >> 2;
    const int c = lane & 3;

    const int q0 = blockIdx.x * 128;
    const int h = blockIdx.y;
    const int b = blockIdx.z;

    // Load Q fragments once (scale folded in).
    const float* Qg = gq + ((size_t)b * TQ + q0 + w * 16) * DOUT + h * HD;
    unsigned QA[8][4];
#pragma unroll
    for (int ks = 0; ks < 8; ks++) {
        int d = ks * 8 + c;
        QA[ks][0] = f2tf(Qg[(size_t)g * DOUT + d] * 0.125f);
        QA[ks][1] = f2tf(Qg[(size_t)(g + 8) * DOUT + d] * 0.125f);
        QA[ks][2] = f2tf(Qg[(size_t)g * DOUT + d + 4] * 0.125f);
        QA[ks][3] = f2tf(Qg[(size_t)(g + 8) * DOUT + d + 4] * 0.125f);
    }

    const float* Kg = gk + (size_t)b * TK * DOUT + h * HD;
    const float* Vg = gv + (size_t)b * TK * DOUT + h * HD;

    float o[8][4];
#pragma unroll
    for (int dt = 0; dt < 8; dt++)
#pragma unroll
        for (int j = 0; j < 4; j++) o[dt][j] = 0.0f;
    float mrow0 = -1e30f, mrow1 = -1e30f, lrow0 = 0.0f, lrow1 = 0.0f;

    const int lkk = tid >> 4;          // 0..15 (x4 over i -> 0..63)
    const int ldc = (tid & 15) * 4;    // 0..60

    for (int kt = 0; kt < TK; kt += 64) {
        __syncthreads();  // prior PV done before K/V overwrite
#pragma unroll
        for (int i = 0; i < 4; i++) {
            int kk = lkk + i * 16;
            float4 kv = *(const float4*)&Kg[(size_t)(kt + kk) * DOUT + ldc];
            float4 vv = *(const float4*)&Vg[(size_t)(kt + kk) * DOUT + ldc];
            Ks[kk * KS_ST + ldc + 0] = f2tf(kv.x);
            Ks[kk * KS_ST + ldc + 1] = f2tf(kv.y);
            Ks[kk * KS_ST + ldc + 2] = f2tf(kv.z);
            Ks[kk * KS_ST + ldc + 3] = f2tf(kv.w);
            Vs[kk * VS_ST + ldc + 0] = f2tf(vv.x);
            Vs[kk * VS_ST + ldc + 1] = f2tf(vv.y);
            Vs[kk * VS_ST + ldc + 2] = f2tf(vv.z);
            Vs[kk * VS_ST + ldc + 3] = f2tf(vv.w);
        }
        __syncthreads();

        // S = Q @ K^T  (s[nt]: keys nt*8.., rows g/g+8 of this warp's 16)
        float s[8][4];
#pragma unroll
        for (int nt = 0; nt < 8; nt++)
#pragma unroll
            for (int j = 0; j < 4; j++) s[nt][j] = 0.0f;
#pragma unroll
        for (int ks = 0; ks < 8; ks++) {
            const int kk = ks * 8;
#pragma unroll
            for (int nt = 0; nt < 8; nt++) {
                unsigned b0 = Ks[(nt * 8 + g) * KS_ST + kk + c];
                unsigned b1 = Ks[(nt * 8 + g) * KS_ST + kk + c + 4];
                mma_tf32(s[nt], QA[ks][0], QA[ks][1], QA[ks][2], QA[ks][3], b0, b1);
            }
        }

        // Online softmax. Thread rows: r0 = g, r1 = g+8 (within warp tile).
        float m0 = -1e30f, m1 = -1e30f;
#pragma unroll
        for (int nt = 0; nt < 8; nt++) {
            m0 = fmaxf(m0, fmaxf(s[nt][0], s[nt][1]));
            m1 = fmaxf(m1, fmaxf(s[nt][2], s[nt][3]));
        }
        m0 = fmaxf(m0, __shfl_xor_sync(0xffffffffu, m0, 1));
        m0 = fmaxf(m0, __shfl_xor_sync(0xffffffffu, m0, 2));
        m1 = fmaxf(m1, __shfl_xor_sync(0xffffffffu, m1, 1));
        m1 = fmaxf(m1, __shfl_xor_sync(0xffffffffu, m1, 2));
        float mn0 = fmaxf(mrow0, m0), mn1 = fmaxf(mrow1, m1);
        float cor0 = __expf(mrow0 - mn0), cor1 = __expf(mrow1 - mn1);
        mrow0 = mn0; mrow1 = mn1;

        float l0 = 0.0f, l1 = 0.0f;
        unsigned* Pr0 = Ps + (w * 16 + g) * PS_ST;
        unsigned* Pr1 = Ps + (w * 16 + g + 8) * PS_ST;
#pragma unroll
        for (int nt = 0; nt < 8; nt++) {
            float p0 = __expf(s[nt][0] - mn0);
            float p1 = __expf(s[nt][1] - mn0);
            float p2 = __expf(s[nt][2] - mn1);
            float p3 = __expf(s[nt][3] - mn1);
            l0 += p0 + p1;
            l1 += p2 + p3;
            int cc = nt * 8 + c * 2;
            Pr0[cc] = f2tf(p0); Pr0[cc + 1] = f2tf(p1);
            Pr1[cc] = f2tf(p2); Pr1[cc + 1] = f2tf(p3);
        }
        l0 += __shfl_xor_sync(0xffffffffu, l0, 1);
        l0 += __shfl_xor_sync(0xffffffffu, l0, 2);
        l1 += __shfl_xor_sync(0xffffffffu, l1, 1);
        l1 += __shfl_xor_sync(0xffffffffu, l1, 2);
        lrow0 = lrow0 * cor0 + l0;
        lrow1 = lrow1 * cor1 + l1;
#pragma unroll
        for (int dt = 0; dt < 8; dt++) {
            o[dt][0] *= cor0; o[dt][1] *= cor0;
            o[dt][2] *= cor1; o[dt][3] *= cor1;
        }
        __syncwarp();  // Ps rows are per-warp; cross-lane visibility only

        // O += P @ V
#pragma unroll
        for (int ks = 0; ks < 8; ks++) {
            const int kk = ks * 8;
            unsigned a0 = Ps[(w * 16 + g) * PS_ST + kk + c];
            unsigned a1 = Ps[(w * 16 + g + 8) * PS_ST + kk + c];
            unsigned a2 = Ps[(w * 16 + g) * PS_ST + kk + c + 4];
            unsigned a3 = Ps[(w * 16 + g + 8) * PS_ST + kk + c + 4];
#pragma unroll
            for (int dt = 0; dt < 8; dt++) {
                unsigned b0 = Vs[(kk + c) * VS_ST + dt * 8 + g];
                unsigned b1 = Vs[(kk + c + 4) * VS_ST + dt * 8 + g];
                mma_tf32(o[dt], a0, a1, a2, a3, b0, b1);
            }
        }
    }

    // Normalize and write x in [B, T, H*HD] layout.
    float inv0 = 1.0f / lrow0, inv1 = 1.0f / lrow1;
    size_t r0 = (size_t)b * TQ + q0 + w * 16 + g;
#pragma unroll
    for (int dt = 0; dt < 8; dt++) {
        int cc = h * HD + dt * 8 + c * 2;
        float2 lo = {o[dt][0] * inv0, o[dt][1] * inv0};
        float2 hi = {o[dt][2] * inv1, o[dt][3] * inv1};
        *(float2*)&gx[r0 * DOUT + cc] = lo;
        *(float2*)&gx[(r0 + 8) * DOUT + cc] = hi;
    }
}

// ---------------------------------------------------------------------------
// Launch
// ---------------------------------------------------------------------------
extern "C" void kernel_launch(void* const* d_in, const int* in_sizes, int n_in,
                              void* d_out, int out_size) {
    const float* q  = (const float*)d_in[0];
    const float* k  = (const float*)d_in[1];
    const float* v  = (const float*)d_in[2];
    const float* Wq = (const float*)d_in[3];
    const float* bq = (const float*)d_in[4];
    const float* Wk = (const float*)d_in[5];
    const float* bk = (const float*)d_in[6];
    const float* Wv = (const float*)d_in[7];
    const float* bv = (const float*)d_in[8];
    const float* Wo = (const float*)d_in[9];
    const float* bo = (const float*)d_in[10];
    float* out = (float*)d_out;

    float *pq, *pk, *pv, *px;
    cudaGetSymbolAddress((void**)&pq, g_q);
    cudaGetSymbolAddress((void**)&pk, g_k);
    cudaGetSymbolAddress((void**)&pv, g_v);
    cudaGetSymbolAddress((void**)&px, g_x);

    dim3 blk(256);
    dim3 gproj(DOUT / 128, (BB * TQ) / 128);

    gemm_tf32_kernel<<<gproj, blk>>>(q, Wq, bq, pq, BB * TQ, DOUT, DIN);
    gemm_tf32_kernel<<<gproj, blk>>>(k, Wk, bk, pk, BB * TK, DOUT, DIN);
    gemm_tf32_kernel<<<gproj, blk>>>(v, Wv, bv, pv, BB * TK, DOUT, DIN);

    cudaFuncSetAttribute(attn_tf32_kernel,
                         cudaFuncAttributeMaxDynamicSharedMemorySize,
                         ATTN_SMEM_BYTES);
    attn_tf32_kernel<<<dim3(TQ / 128, NH, BB), blk, ATTN_SMEM_BYTES>>>(pq, pk, pv, px);

    gemm_tf32_kernel<<<gproj, blk>>>(px, Wo, bo, out, BB * TQ, DOUT, DOUT);
}